// round 4
// baseline (speedup 1.0000x reference)
#include <cuda_runtime.h>

#define DIM 496
#define SPITCH 504   // padded smem row pitch (floats); 504%32=24 -> conflict-free f4

__device__ float g_cs[16];
__device__ float g_sn[16];

// pair index of (x,y), x<y, in itertools.combinations(range(32),2) order
__device__ __forceinline__ int pidx(int x, int y) {
    return x * 31 - ((x * (x - 1)) >> 1) + (y - x - 1);
}

// Decode orbit o in [0,124): member basis indices m[0..3] as m[alpha*2+beta];
// outer gate gO acts on alpha (pairs (0,2),(1,3)), inner gI on beta ((0,1),(2,3)).
// Gate 15 == identity.
__device__ __forceinline__ void decode_orbit(int o, int m[4], int& gO, int& gI) {
    if (o < 105) {                       // cross-block (g<h<15): R_g (x) R_h
        int g = 0, rem = o;
        while (rem >= 14 - g) { rem -= 14 - g; ++g; }
        int h = g + 1 + rem;
        gO = g; gI = h;
        m[0] = pidx(2 * g,     2 * h);
        m[1] = pidx(2 * g,     2 * h + 1);
        m[2] = pidx(2 * g + 1, 2 * h);
        m[3] = pidx(2 * g + 1, 2 * h + 1);
    } else if (o < 120) {                // block g with qubits 30/31: R_g (x) I
        int g = o - 105;
        gO = g; gI = 15;
        m[0] = pidx(2 * g,     30);
        m[1] = pidx(2 * g,     31);
        m[2] = pidx(2 * g + 1, 30);
        m[3] = pidx(2 * g + 1, 31);
    } else {                             // 16 identity singletons, 4 per orbit
        int j = o - 120;
        gO = 15; gI = 15;
#pragma unroll
        for (int k = 0; k < 4; ++k) {
            int q = 4 * j + k;
            m[k] = pidx(2 * q, 2 * q + 1);
        }
    }
}

__global__ void rbs_angles_kernel(const float* __restrict__ angles) {
    int t = threadIdx.x;
    if (t < 15) {
        float s, c;
        sincosf(angles[t], &s, &c);
        g_cs[t] = c; g_sn[t] = s;
    } else if (t == 15) {
        g_cs[15] = 1.0f; g_sn[15] = 0.0f;
    }
}

// Block = (row-orbit ro, batch b), 512 threads.
// Thread t: row i = t&3 of the orbit, float4 chunk j = t>>2 (active j<124).
// Row rotation entirely via shfl (partners at lane^1, lane^2) -> no barrier.
// Column rotation via one padded-smem round-trip. 2 barriers total.
__global__ __launch_bounds__(512) void rbs_density_kernel(
    const float* __restrict__ rho, float* __restrict__ out)
{
    __shared__ float S[4][SPITCH];

    const int t  = threadIdx.x;
    const int i  = t & 3;
    const int j  = t >> 2;
    const bool act = (j < 124);
    const int ro = blockIdx.x;
    const int b  = blockIdx.y;

    int rm[4], rgO, rgI;
    decode_orbit(ro, rm, rgO, rgI);

    const size_t boff = (size_t)b * DIM * DIM;

    float4 v = make_float4(0.f, 0.f, 0.f, 0.f);
    if (act)
        v = ((const float4*)(rho + boff + (size_t)rm[i] * DIM))[j];

    // Row transform via warp shuffles. ALL 512 threads execute the shfls
    // (full mask); inactive lanes carry garbage that is never stored.
    {
        const float ci = __ldg(&g_cs[rgI]);
        const float co = __ldg(&g_cs[rgO]);
        const float s1 = (i & 1) ? -__ldg(&g_sn[rgI]) : __ldg(&g_sn[rgI]);
        const float s2 = (i & 2) ? -__ldg(&g_sn[rgO]) : __ldg(&g_sn[rgO]);

        float4 p;   // inner partner (beta flip, lane^1)
        p.x = __shfl_xor_sync(0xFFFFFFFFu, v.x, 1);
        p.y = __shfl_xor_sync(0xFFFFFFFFu, v.y, 1);
        p.z = __shfl_xor_sync(0xFFFFFFFFu, v.z, 1);
        p.w = __shfl_xor_sync(0xFFFFFFFFu, v.w, 1);
        v.x = ci * v.x + s1 * p.x;  v.y = ci * v.y + s1 * p.y;
        v.z = ci * v.z + s1 * p.z;  v.w = ci * v.w + s1 * p.w;

        float4 q;   // outer partner (alpha flip, lane^2)
        q.x = __shfl_xor_sync(0xFFFFFFFFu, v.x, 2);
        q.y = __shfl_xor_sync(0xFFFFFFFFu, v.y, 2);
        q.z = __shfl_xor_sync(0xFFFFFFFFu, v.z, 2);
        q.w = __shfl_xor_sync(0xFFFFFFFFu, v.w, 2);
        v.x = co * v.x + s2 * q.x;  v.y = co * v.y + s2 * q.y;
        v.z = co * v.z + s2 * q.z;  v.w = co * v.w + s2 * q.w;
    }

    if (act)
        *(float4*)&S[i][4 * j] = v;
    __syncthreads();

    // Column transform: thread t -> (row i2, col-orbit c); disjoint 4-column
    // sets per orbit -> in-place safe.
    if (t < 496) {
        const int i2 = t / 124;
        const int c  = t - 124 * i2;
        int cm[4], cgO, cgI;
        decode_orbit(c, cm, cgO, cgI);
        const float ci = __ldg(&g_cs[cgI]), si = __ldg(&g_sn[cgI]);
        const float co = __ldg(&g_cs[cgO]), so = __ldg(&g_sn[cgO]);

        float w0 = S[i2][cm[0]], w1 = S[i2][cm[1]];
        float w2 = S[i2][cm[2]], w3 = S[i2][cm[3]];
        float t0 = ci * w0 + si * w1, t1 = ci * w1 - si * w0;
        float t2 = ci * w2 + si * w3, t3 = ci * w3 - si * w2;
        S[i2][cm[0]] = co * t0 + so * t2;  S[i2][cm[2]] = co * t2 - so * t0;
        S[i2][cm[1]] = co * t1 + so * t3;  S[i2][cm[3]] = co * t3 - so * t1;
    }
    __syncthreads();

    if (act)
        ((float4*)(out + boff + (size_t)rm[i] * DIM))[j] =
            *(const float4*)&S[i][4 * j];
}

extern "C" void kernel_launch(void* const* d_in, const int* in_sizes, int n_in,
                              void* d_out, int out_size) {
    const float* rho = (const float*)d_in[0];
    const float* ang = (const float*)d_in[1];
    if (n_in >= 2 && in_sizes[0] == 15) {   // defensive input-order swap
        rho = (const float*)d_in[1];
        ang = (const float*)d_in[0];
    }
    rbs_angles_kernel<<<1, 32>>>(ang);
    dim3 grid(124, 8);
    rbs_density_kernel<<<grid, 512>>>(rho, (float*)d_out);
}

// round 5
// speedup vs baseline: 1.2625x; 1.2625x over previous
#include <cuda_runtime.h>

#define DIM 496
#define SPITCH 504   // padded smem row pitch (floats); 504*4B=2016B, 16B-aligned rows
#define NB 4         // batches per block

// pair index of (x,y), x<y, in itertools.combinations(range(32),2) order
__device__ __forceinline__ int pidx(int x, int y) {
    return x * 31 - ((x * (x - 1)) >> 1) + (y - x - 1);
}

// Decode orbit o in [0,124): member basis indices m[0..3] as m[alpha*2+beta];
// outer gate gO acts on alpha (pairs (0,2),(1,3)), inner gI on beta ((0,1),(2,3)).
// Gate 15 == identity.
__device__ __forceinline__ void decode_orbit(int o, int m[4], int& gO, int& gI) {
    if (o < 105) {                       // cross-block (g<h<15): R_g (x) R_h
        int g = 0, rem = o;
        while (rem >= 14 - g) { rem -= 14 - g; ++g; }
        int h = g + 1 + rem;
        gO = g; gI = h;
        m[0] = pidx(2 * g,     2 * h);
        m[1] = pidx(2 * g,     2 * h + 1);
        m[2] = pidx(2 * g + 1, 2 * h);
        m[3] = pidx(2 * g + 1, 2 * h + 1);
    } else if (o < 120) {                // block g with qubits 30/31: R_g (x) I
        int g = o - 105;
        gO = g; gI = 15;
        m[0] = pidx(2 * g,     30);
        m[1] = pidx(2 * g,     31);
        m[2] = pidx(2 * g + 1, 30);
        m[3] = pidx(2 * g + 1, 31);
    } else {                             // 16 identity singletons, 4 per orbit
        int j = o - 120;
        gO = 15; gI = 15;
#pragma unroll
        for (int k = 0; k < 4; ++k) {
            int q = 4 * j + k;
            m[k] = pidx(2 * q, 2 * q + 1);
        }
    }
}

__device__ __forceinline__ void gate_cs(const float* __restrict__ angles,
                                        int g, float& c, float& s) {
    if (g < 15) sincosf(__ldg(angles + g), &s, &c);
    else { c = 1.0f; s = 0.0f; }
}

// Block = (row-orbit ro) x (4 batches). 128 threads; thread t = float4 chunk
// (active t<124). 16 independent LDG.128 per thread front-batched for MLP.
__global__ __launch_bounds__(128) void rbs_density_kernel(
    const float* __restrict__ rho, const float* __restrict__ angles,
    float* __restrict__ out)
{
    __shared__ __align__(16) float S[NB][4][SPITCH];   // 32.25 KB

    const int t  = threadIdx.x;
    const int ro = blockIdx.x;
    const int b0 = blockIdx.y * NB;

    int rm[4], rgO, rgI;
    decode_orbit(ro, rm, rgO, rgI);

    if (t < 124) {
        // Phase 1: 16 independent loads, all in flight at once.
        float4 v[NB][4];
#pragma unroll
        for (int b2 = 0; b2 < NB; ++b2) {
            const float* base = rho + (size_t)(b0 + b2) * DIM * DIM;
#pragma unroll
            for (int i = 0; i < 4; ++i)
                v[b2][i] = ((const float4*)(base + (size_t)rm[i] * DIM))[t];
        }

        // Row transform in registers.
        float ci, si, co, so;
        gate_cs(angles, rgI, ci, si);
        gate_cs(angles, rgO, co, so);
#pragma unroll
        for (int b2 = 0; b2 < NB; ++b2) {
#pragma unroll
            for (int k = 0; k < 4; ++k) {
                float v0 = ((float*)&v[b2][0])[k], v1 = ((float*)&v[b2][1])[k];
                float v2 = ((float*)&v[b2][2])[k], v3 = ((float*)&v[b2][3])[k];
                float t0 = ci * v0 + si * v1, t1 = ci * v1 - si * v0;
                float t2 = ci * v2 + si * v3, t3 = ci * v3 - si * v2;
                ((float*)&v[b2][0])[k] = co * t0 + so * t2;
                ((float*)&v[b2][2])[k] = co * t2 - so * t0;
                ((float*)&v[b2][1])[k] = co * t1 + so * t3;
                ((float*)&v[b2][3])[k] = co * t3 - so * t1;
            }
#pragma unroll
            for (int i = 0; i < 4; ++i)
                *(float4*)&S[b2][i][4 * t] = v[b2][i];
        }
    }
    __syncthreads();

    // Phase 2: column transform in smem. Thread t owns col-orbit t (disjoint
    // 4-column sets -> in-place safe), looping over 4 batches x 4 rows.
    if (t < 124) {
        int cm[4], cgO, cgI;
        decode_orbit(t, cm, cgO, cgI);
        float ci, si, co, so;
        gate_cs(angles, cgI, ci, si);
        gate_cs(angles, cgO, co, so);
#pragma unroll
        for (int b2 = 0; b2 < NB; ++b2) {
#pragma unroll
            for (int i2 = 0; i2 < 4; ++i2) {
                float* row = S[b2][i2];
                float w0 = row[cm[0]], w1 = row[cm[1]];
                float w2 = row[cm[2]], w3 = row[cm[3]];
                float t0 = ci * w0 + si * w1, t1 = ci * w1 - si * w0;
                float t2 = ci * w2 + si * w3, t3 = ci * w3 - si * w2;
                row[cm[0]] = co * t0 + so * t2;  row[cm[2]] = co * t2 - so * t0;
                row[cm[1]] = co * t1 + so * t3;  row[cm[3]] = co * t3 - so * t1;
            }
        }
    }
    __syncthreads();

    // Phase 3: coalesced float4 stores.
    if (t < 124) {
#pragma unroll
        for (int b2 = 0; b2 < NB; ++b2) {
            float* obase = out + (size_t)(b0 + b2) * DIM * DIM;
#pragma unroll
            for (int i = 0; i < 4; ++i)
                ((float4*)(obase + (size_t)rm[i] * DIM))[t] =
                    *(const float4*)&S[b2][i][4 * t];
        }
    }
}

extern "C" void kernel_launch(void* const* d_in, const int* in_sizes, int n_in,
                              void* d_out, int out_size) {
    const float* rho = (const float*)d_in[0];
    const float* ang = (const float*)d_in[1];
    if (n_in >= 2 && in_sizes[0] == 15) {   // defensive input-order swap
        rho = (const float*)d_in[1];
        ang = (const float*)d_in[0];
    }
    dim3 grid(124, 2);
    rbs_density_kernel<<<grid, 128>>>(rho, ang, (float*)d_out);
}

// round 6
// speedup vs baseline: 1.5188x; 1.2030x over previous
#include <cuda_runtime.h>
#include <cstdint>

#define DIM 496
#define ROW_BYTES (DIM * 4)   // 1984, multiple of 16

// pair index of (x,y), x<y, in itertools.combinations(range(32),2) order
__device__ __forceinline__ int pidx(int x, int y) {
    return x * 31 - ((x * (x - 1)) >> 1) + (y - x - 1);
}

// Decode orbit o in [0,124): member basis indices m[0..3] as m[alpha*2+beta];
// outer gate gO acts on alpha (pairs (0,2),(1,3)), inner gI on beta ((0,1),(2,3)).
// Gate 15 == identity.
__device__ __forceinline__ void decode_orbit(int o, int m[4], int& gO, int& gI) {
    if (o < 105) {                       // cross-block (g<h<15): R_g (x) R_h
        int g = 0, rem = o;
        while (rem >= 14 - g) { rem -= 14 - g; ++g; }
        int h = g + 1 + rem;
        gO = g; gI = h;
        m[0] = pidx(2 * g,     2 * h);
        m[1] = pidx(2 * g,     2 * h + 1);
        m[2] = pidx(2 * g + 1, 2 * h);
        m[3] = pidx(2 * g + 1, 2 * h + 1);
    } else if (o < 120) {                // block g with qubits 30/31: R_g (x) I
        int g = o - 105;
        gO = g; gI = 15;
        m[0] = pidx(2 * g,     30);
        m[1] = pidx(2 * g,     31);
        m[2] = pidx(2 * g + 1, 30);
        m[3] = pidx(2 * g + 1, 31);
    } else {                             // 16 identity singletons, 4 per orbit
        int j = o - 120;
        gO = 15; gI = 15;
#pragma unroll
        for (int k = 0; k < 4; ++k) {
            int q = 4 * j + k;
            m[k] = pidx(2 * q, 2 * q + 1);
        }
    }
}

__device__ __forceinline__ void gate_cs(const float* __restrict__ angles,
                                        int g, float& c, float& s) {
    if (g < 15) sincosf(__ldg(angles + g), &s, &c);
    else { c = 1.0f; s = 0.0f; }
}

__device__ __forceinline__ uint32_t smem_u32(const void* p) {
    return (uint32_t)__cvta_generic_to_shared(p);
}

// Block = (row-orbit ro, batch b), 128 threads. All HBM traffic via bulk-async
// (TMA path): 4 row loads against an mbarrier, 4 row stores via bulk_group.
__global__ __launch_bounds__(128) void rbs_density_kernel(
    const float* __restrict__ rho, const float* __restrict__ angles,
    float* __restrict__ out)
{
    __shared__ __align__(16) float S[4][DIM];   // 7936 B
    __shared__ __align__(8) uint64_t mbar;

    const int t  = threadIdx.x;
    const int ro = blockIdx.x;
    const int b  = blockIdx.y;

    int rm[4], rgO, rgI;
    decode_orbit(ro, rm, rgO, rgI);

    const size_t boff = (size_t)b * DIM * DIM;
    const uint32_t mbar_a = smem_u32(&mbar);

    // Init mbarrier, then launch the 4 bulk loads from one thread.
    if (t == 0) {
        asm volatile("mbarrier.init.shared.b64 [%0], 1;" :: "r"(mbar_a) : "memory");
        asm volatile("fence.proxy.async.shared::cta;" ::: "memory");
        asm volatile("mbarrier.arrive.expect_tx.shared.b64 _, [%0], %1;"
                     :: "r"(mbar_a), "r"(4 * ROW_BYTES) : "memory");
#pragma unroll
        for (int i = 0; i < 4; ++i) {
            const float* src = rho + boff + (size_t)rm[i] * DIM;
            asm volatile(
                "cp.async.bulk.shared::cluster.global.mbarrier::complete_tx::bytes "
                "[%0], [%1], %2, [%3];"
                :: "r"(smem_u32(S[i])), "l"(src), "r"(ROW_BYTES), "r"(mbar_a)
                : "memory");
        }
    }

    // Overlap: trig + column-orbit decode while the copy is in flight.
    float rci, rsi, rco, rso;
    gate_cs(angles, rgI, rci, rsi);
    gate_cs(angles, rgO, rco, rso);

    int cm[4], cgO, cgI;
    float cci = 1.f, csi = 0.f, cco = 1.f, cso = 0.f;
    if (t < 124) {
        decode_orbit(t, cm, cgO, cgI);
        gate_cs(angles, cgI, cci, csi);
        gate_cs(angles, cgO, cco, cso);
    }

    __syncthreads();                     // mbar.init visible to all waiters

    // Wait for load completion (phase 0), acquire semantics.
    {
        uint32_t done;
        asm volatile(
            "{\n\t.reg .pred p;\n\t"
            "mbarrier.try_wait.parity.acquire.cta.shared::cta.b64 p, [%1], 0;\n\t"
            "selp.b32 %0, 1, 0, p;\n\t}"
            : "=r"(done) : "r"(mbar_a) : "memory");
        while (!done) {
            asm volatile(
                "{\n\t.reg .pred p;\n\t"
                "mbarrier.try_wait.parity.acquire.cta.shared::cta.b64 p, [%1], 0, 0x989680;\n\t"
                "selp.b32 %0, 1, 0, p;\n\t}"
                : "=r"(done) : "r"(mbar_a) : "memory");
        }
    }

    // Row transform in smem: each thread a strided set of columns.
    for (int c = t; c < DIM; c += 128) {
        float v0 = S[0][c], v1 = S[1][c], v2 = S[2][c], v3 = S[3][c];
        float t0 = rci * v0 + rsi * v1, t1 = rci * v1 - rsi * v0;
        float t2 = rci * v2 + rsi * v3, t3 = rci * v3 - rsi * v2;
        S[0][c] = rco * t0 + rso * t2;  S[2][c] = rco * t2 - rso * t0;
        S[1][c] = rco * t1 + rso * t3;  S[3][c] = rco * t3 - rso * t1;
    }
    __syncthreads();

    // Column transform: thread t owns col-orbit t (disjoint 4-col sets).
    if (t < 124) {
#pragma unroll
        for (int i = 0; i < 4; ++i) {
            float w0 = S[i][cm[0]], w1 = S[i][cm[1]];
            float w2 = S[i][cm[2]], w3 = S[i][cm[3]];
            float t0 = cci * w0 + csi * w1, t1 = cci * w1 - csi * w0;
            float t2 = cci * w2 + csi * w3, t3 = cci * w3 - csi * w2;
            S[i][cm[0]] = cco * t0 + cso * t2;  S[i][cm[2]] = cco * t2 - cso * t0;
            S[i][cm[1]] = cco * t1 + cso * t3;  S[i][cm[3]] = cco * t3 - cso * t1;
        }
    }
    __syncthreads();

    // Bulk stores (shared -> global) from one thread, then drain.
    if (t == 0) {
        asm volatile("fence.proxy.async.shared::cta;" ::: "memory");
#pragma unroll
        for (int i = 0; i < 4; ++i) {
            float* dst = out + boff + (size_t)rm[i] * DIM;
            asm volatile(
                "cp.async.bulk.global.shared::cta.bulk_group [%0], [%1], %2;"
                :: "l"(dst), "r"(smem_u32(S[i])), "r"(ROW_BYTES)
                : "memory");
        }
        asm volatile("cp.async.bulk.commit_group;" ::: "memory");
        asm volatile("cp.async.bulk.wait_group 0;" ::: "memory");
    }
}

extern "C" void kernel_launch(void* const* d_in, const int* in_sizes, int n_in,
                              void* d_out, int out_size) {
    const float* rho = (const float*)d_in[0];
    const float* ang = (const float*)d_in[1];
    if (n_in >= 2 && in_sizes[0] == 15) {   // defensive input-order swap
        rho = (const float*)d_in[1];
        ang = (const float*)d_in[0];
    }
    dim3 grid(124, 8);
    rbs_density_kernel<<<grid, 128>>>(rho, ang, (float*)d_out);
}